// round 1
// baseline (speedup 1.0000x reference)
#include <cuda_runtime.h>

typedef unsigned long long u64;

#define NK 16
#define TW 516            // tile row stride (514 used, +2 pad)
#define GAINF 10.0f
#define LOG2E 1.44269504088896f

__device__ __forceinline__ u64 pack2(float lo, float hi) {
    u64 r; asm("mov.b64 %0, {%1, %2};" : "=l"(r) : "f"(lo), "f"(hi)); return r;
}
__device__ __forceinline__ void unpack2(u64 v, float& lo, float& hi) {
    asm("mov.b64 {%0, %1}, %2;" : "=f"(lo), "=f"(hi) : "l"(v));
}
__device__ __forceinline__ u64 fma2(u64 a, u64 b, u64 c) {
    u64 d; asm("fma.rn.f32x2 %0, %1, %2, %3;" : "=l"(d) : "l"(a), "l"(b), "l"(c)); return d;
}
__device__ __forceinline__ u64 mul2_(u64 a, u64 b) {
    u64 d; asm("mul.rn.f32x2 %0, %1, %2;" : "=l"(d) : "l"(a), "l"(b)); return d;
}
__device__ __forceinline__ u64 add2_(u64 a, u64 b) {
    u64 d; asm("add.rn.f32x2 %0, %1, %2;" : "=l"(d) : "l"(a), "l"(b)); return d;
}
__device__ __forceinline__ float ex2_(float a) {
    float r; asm("ex2.approx.f32 %0, %1;" : "=f"(r) : "f"(a)); return r;
}
__device__ __forceinline__ float rcp_(float a) {
    float r; asm("rcp.approx.f32 %0, %1;" : "=f"(r) : "f"(a)); return r;
}

// Grid: (128 row-tiles, 16 batch). Block: (64, 4). Each thread: 8 pixels (4 f32x2 pairs).
__global__ void __launch_bounds__(256, 2)
ca_kernel(const float* __restrict__ x, const float* __restrict__ w,
          const float* __restrict__ react, const float* __restrict__ prod,
          float* __restrict__ out)
{
    __shared__ float tile[6][TW];
    __shared__ u64 wk[NK][9];   // conv weights, duplicated (w,w)
    __shared__ u64 ek[NK];      // +GAIN*LOG2E*reactant[k], duplicated
    __shared__ u64 pk[NK];      // products[k], duplicated

    const int b   = blockIdx.y;
    const int y0  = blockIdx.x * 4;
    const int tid = threadIdx.y * 64 + threadIdx.x;

    // Stage constants into shared (packed/duplicated for f32x2 operands)
    if (tid < NK * 9) {
        int k = tid / 9, t = tid - k * 9;
        float v = w[k * 9 + t];
        wk[k][t] = pack2(v, v);
    } else if (tid < NK * 10) {
        int k = tid - NK * 9;
        float v = GAINF * LOG2E * react[k];
        ek[k] = pack2(v, v);
    } else if (tid < NK * 11) {
        int k = tid - NK * 10;
        float v = prod[k];
        pk[k] = pack2(v, v);
    }

    // Load input tile: rows y0-1 .. y0+4, cols -1..512, zero-padded boundary
    const float* xb = x + (size_t)b * (512 * 512);
    for (int i = tid; i < 6 * 514; i += 256) {
        int r  = i / 514;
        int c  = i - r * 514;        // tile col 0..513; global col = c-1
        int gy = y0 - 1 + r;
        int gx = c - 1;
        float v = 0.0f;
        if ((unsigned)gy < 512u && (unsigned)gx < 512u)
            v = xb[gy * 512 + gx];
        tile[r][c] = v;
    }
    __syncthreads();

    const int tx = threadIdx.x * 8;  // tile col index of (global col - 1) window start
    const int ty = threadIdx.y;

    // Register neighborhood: 3 rows x 9 shifted float2 windows.
    // nb[r][o] = (tile[ty+r][tx+o], tile[ty+r][tx+o+1]); pair p tap dx -> nb[r][2p+dx]
    u64 nb[3][9];
    #pragma unroll
    for (int r = 0; r < 3; r++) {
        float v[10];
        #pragma unroll
        for (int c = 0; c < 10; c++) v[c] = tile[ty + r][tx + c];
        #pragma unroll
        for (int o = 0; o < 9; o++) nb[r][o] = pack2(v[o], v[o + 1]);
    }

    const u64 NGL = pack2(-GAINF * LOG2E, -GAINF * LOG2E);

    u64 accP[4], accS[4];   // sum(s_k * p_k), sum(s_k)
    #pragma unroll
    for (int p = 0; p < 4; p++) { accP[p] = 0ull; accS[p] = 0ull; }

    #pragma unroll
    for (int k = 0; k < NK; k++) {
        u64 wv[9];
        #pragma unroll
        for (int t = 0; t < 9; t++) wv[t] = wk[k][t];
        const u64 ekk = ek[k];
        const u64 pkk = pk[k];
        #pragma unroll
        for (int p = 0; p < 4; p++) {
            u64 n2 = mul2_(wv[0], nb[0][2 * p]);
            n2 = fma2(wv[1], nb[0][2 * p + 1], n2);
            n2 = fma2(wv[2], nb[0][2 * p + 2], n2);
            n2 = fma2(wv[3], nb[1][2 * p],     n2);
            n2 = fma2(wv[4], nb[1][2 * p + 1], n2);
            n2 = fma2(wv[5], nb[1][2 * p + 2], n2);
            n2 = fma2(wv[6], nb[2][2 * p],     n2);
            n2 = fma2(wv[7], nb[2][2 * p + 1], n2);
            n2 = fma2(wv[8], nb[2][2 * p + 2], n2);
            // ex2 argument: -GAIN*log2e*(N - r) folded into one packed FMA
            u64 z2 = fma2(n2, NGL, ekk);
            float z0, z1; unpack2(z2, z0, z1);
            float s0 = rcp_(1.0f + ex2_(z0));   // sigmoid(GAIN*(N-r))
            float s1 = rcp_(1.0f + ex2_(z1));
            u64 s2 = pack2(s0, s1);
            accP[p] = fma2(s2, pkk, accP[p]);
            accS[p] = add2_(s2, accS[p]);
        }
    }

    // Epilogue: out = clamp(x + accP - x*accS, 0, 1)
    float* ob = out + (size_t)b * (512 * 512) + (size_t)(y0 + ty) * 512 + tx;
    float res[8];
    const u64 NEG1 = pack2(-1.0f, -1.0f);
    #pragma unroll
    for (int p = 0; p < 4; p++) {
        u64 x2   = nb[1][2 * p + 1];            // center pair
        u64 negs = mul2_(accS[p], NEG1);
        u64 d2   = fma2(x2, negs, accP[p]);     // accP - x*accS
        u64 o2   = add2_(x2, d2);
        float o0, o1; unpack2(o2, o0, o1);
        res[2 * p]     = __saturatef(o0);
        res[2 * p + 1] = __saturatef(o1);
    }
    ((float4*)ob)[0] = make_float4(res[0], res[1], res[2], res[3]);
    ((float4*)ob)[1] = make_float4(res[4], res[5], res[6], res[7]);
}

extern "C" void kernel_launch(void* const* d_in, const int* in_sizes, int n_in,
                              void* d_out, int out_size) {
    const float* x = (const float*)d_in[0];
    const float* w = (const float*)d_in[1];
    const float* r = (const float*)d_in[2];
    const float* p = (const float*)d_in[3];
    dim3 grid(128, 16);   // 512/4 row tiles, 16 batch images
    dim3 block(64, 4);
    ca_kernel<<<grid, block>>>(x, w, r, p, (float*)d_out);
}

// round 2
// speedup vs baseline: 1.3980x; 1.3980x over previous
#include <cuda_runtime.h>

typedef unsigned long long u64;

#define NK 16
#define TW 516            // tile row stride (514 used, +2 pad)

__device__ __forceinline__ u64 pack2(float lo, float hi) {
    u64 r; asm("mov.b64 %0, {%1, %2};" : "=l"(r) : "f"(lo), "f"(hi)); return r;
}
__device__ __forceinline__ void unpack2(u64 v, float& lo, float& hi) {
    asm("mov.b64 {%0, %1}, %2;" : "=f"(lo), "=f"(hi) : "l"(v));
}
__device__ __forceinline__ u64 fma2(u64 a, u64 b, u64 c) {
    u64 d; asm("fma.rn.f32x2 %0, %1, %2, %3;" : "=l"(d) : "l"(a), "l"(b), "l"(c)); return d;
}
__device__ __forceinline__ u64 mul2_(u64 a, u64 b) {
    u64 d; asm("mul.rn.f32x2 %0, %1, %2;" : "=l"(d) : "l"(a), "l"(b)); return d;
}
__device__ __forceinline__ u64 add2_(u64 a, u64 b) {
    u64 d; asm("add.rn.f32x2 %0, %1, %2;" : "=l"(d) : "l"(a), "l"(b)); return d;
}
__device__ __forceinline__ float tanh_(float a) {
    float r; asm("tanh.approx.f32 %0, %1;" : "=f"(r) : "f"(a)); return r;
}

// Grid: (256 row-tiles of 2 rows, 16 batch). Block: (128, 2).
// Each thread: 4 pixels in one row (2 f32x2 pairs).
__global__ void __launch_bounds__(256, 4)
ca_kernel(const float* __restrict__ x, const float* __restrict__ w,
          const float* __restrict__ react, const float* __restrict__ prod,
          float* __restrict__ out)
{
    __shared__ float tile[4][TW];
    __shared__ u64 wk[NK][9];    // conv weights, duplicated (w,w)
    __shared__ u64 mrk[NK];      // (-5*reactant, -5*reactant)
    __shared__ u64 pk[NK];       // (0.5*product, 0.5*product)
    __shared__ float psumh;      // 0.5 * sum(products)

    const int b   = blockIdx.y;
    const int y0  = blockIdx.x * 2;
    const int tid = threadIdx.y * 128 + threadIdx.x;

    // Stage constants into shared (packed/duplicated for f32x2 operands)
    if (tid < NK * 9) {
        int k = tid / 9, t = tid - k * 9;
        float v = w[k * 9 + t];
        wk[k][t] = pack2(v, v);
    } else if (tid < NK * 10) {
        int k = tid - NK * 9;
        float v = -5.0f * react[k];          // z = 5N - 5r
        mrk[k] = pack2(v, v);
    } else if (tid < NK * 11) {
        int k = tid - NK * 10;
        float v = 0.5f * prod[k];
        pk[k] = pack2(v, v);
    } else if (tid == NK * 11) {
        float s = 0.0f;
        #pragma unroll
        for (int k = 0; k < NK; k++) s += prod[k];
        psumh = 0.5f * s;
    }

    // Load input tile: rows y0-1 .. y0+2, cols -1..512, zero-padded boundary
    const float* xb = x + (size_t)b * (512 * 512);
    for (int i = tid; i < 4 * 514; i += 256) {
        int r  = i / 514;
        int c  = i - r * 514;        // tile col 0..513; global col = c-1
        int gy = y0 - 1 + r;
        int gx = c - 1;
        float v = 0.0f;
        if ((unsigned)gy < 512u && (unsigned)gx < 512u)
            v = xb[gy * 512 + gx];
        tile[r][c] = v;
    }
    __syncthreads();

    const int tx0 = threadIdx.x * 4;   // global col base; tile col of (gx-1) = tx0
    const int ty  = threadIdx.y;

    // Register neighborhood: 3 rows x 5 shifted float2 windows.
    // nb[r][o] = (v[o], v[o+1]) where v[j] = tile[ty+r][tx0+j] (j=0..5).
    // Pair p (pixels 2p,2p+1), tap (r,dx): nb[r][2p + dx + 1].
    u64 nb[3][5];
    #pragma unroll
    for (int r = 0; r < 3; r++) {
        float v[6];
        #pragma unroll
        for (int c = 0; c < 6; c++) v[c] = tile[ty + r][tx0 + c];
        #pragma unroll
        for (int o = 0; o < 5; o++) nb[r][o] = pack2(v[o], v[o + 1]);
    }

    const u64 FIVE2 = pack2(5.0f, 5.0f);
    const u64 MH2   = pack2(-0.5f, -0.5f);

    u64 accP0 = 0ull, accP1 = 0ull;   // sum( t_k * 0.5*p_k )
    u64 accT0 = 0ull, accT1 = 0ull;   // sum( -0.5 * t_k )

    #pragma unroll
    for (int k = 0; k < NK; k++) {
        // Conv: stream one weight pair at a time (1 live wv, 2 partial sums)
        u64 wv = wk[k][0];
        u64 a0 = mul2_(wv, nb[0][0]);
        u64 a1 = mul2_(wv, nb[0][2]);
        #pragma unroll
        for (int t = 1; t < 9; t++) {
            int r = t / 3, c = t - 3 * r;
            wv = wk[k][t];
            a0 = fma2(wv, nb[r][c],     a0);
            a1 = fma2(wv, nb[r][c + 2], a1);
        }
        const u64 mk  = mrk[k];
        const u64 pkk = pk[k];
        // z = 5*N - 5*r ; s = 0.5 + 0.5*tanh(z) (folded into epilogue)
        u64 z0 = fma2(a0, FIVE2, mk);
        u64 z1 = fma2(a1, FIVE2, mk);
        float za, zb, zc, zd;
        unpack2(z0, za, zb);
        unpack2(z1, zc, zd);
        u64 t0 = pack2(tanh_(za), tanh_(zb));
        u64 t1 = pack2(tanh_(zc), tanh_(zd));
        accP0 = fma2(t0, pkk, accP0);
        accP1 = fma2(t1, pkk, accP1);
        accT0 = fma2(t0, MH2, accT0);
        accT1 = fma2(t1, MH2, accT1);
    }

    // Epilogue: out = clamp( 0.5*sum(p) + accP + x*(accT - 7), 0, 1 )
    const float ps = psumh;
    const u64 PS2 = pack2(ps, ps);
    const u64 M72 = pack2(-7.0f, -7.0f);

    float* ob = out + (size_t)b * (512 * 512) + (size_t)(y0 + ty) * 512 + tx0;

    u64 x20 = nb[1][1], x21 = nb[1][3];   // center pairs
    u64 h0 = add2_(accT0, M72);
    u64 h1 = add2_(accT1, M72);
    u64 o0 = add2_(fma2(x20, h0, accP0), PS2);
    u64 o1 = add2_(fma2(x21, h1, accP1), PS2);

    float r0, r1, r2, r3;
    unpack2(o0, r0, r1);
    unpack2(o1, r2, r3);
    ((float4*)ob)[0] = make_float4(__saturatef(r0), __saturatef(r1),
                                   __saturatef(r2), __saturatef(r3));
}

extern "C" void kernel_launch(void* const* d_in, const int* in_sizes, int n_in,
                              void* d_out, int out_size) {
    const float* x = (const float*)d_in[0];
    const float* w = (const float*)d_in[1];
    const float* r = (const float*)d_in[2];
    const float* p = (const float*)d_in[3];
    dim3 grid(256, 16);   // 512/2 row tiles, 16 batch images
    dim3 block(128, 2);
    ca_kernel<<<grid, block>>>(x, w, r, p, (float*)d_out);
}

// round 3
// speedup vs baseline: 1.6496x; 1.1800x over previous
#include <cuda_runtime.h>

typedef unsigned long long u64;

#define NK 16
#define TW 520            // tile row stride in floats (cols 3..516 used; gx -> gx+4)

__device__ __forceinline__ u64 pack2(float lo, float hi) {
    u64 r; asm("mov.b64 %0, {%1, %2};" : "=l"(r) : "f"(lo), "f"(hi)); return r;
}
__device__ __forceinline__ void unpack2(u64 v, float& lo, float& hi) {
    asm("mov.b64 {%0, %1}, %2;" : "=f"(lo), "=f"(hi) : "l"(v));
}
__device__ __forceinline__ u64 fma2(u64 a, u64 b, u64 c) {
    u64 d; asm("fma.rn.f32x2 %0, %1, %2, %3;" : "=l"(d) : "l"(a), "l"(b), "l"(c)); return d;
}
__device__ __forceinline__ u64 add2_(u64 a, u64 b) {
    u64 d; asm("add.rn.f32x2 %0, %1, %2;" : "=l"(d) : "l"(a), "l"(b)); return d;
}
__device__ __forceinline__ float tanh_(float a) {
    float r; asm("tanh.approx.f32 %0, %1;" : "=f"(r) : "f"(a)); return r;
}

// Grid: (128 tiles of 4 rows, 16 batch). Block: (128, 2) = 256 threads.
// Each thread: 2 rows x 4 cols = 8 pixels (4 f32x2 pairs).
__global__ void __launch_bounds__(256, 3)
ca_kernel(const float* __restrict__ x, const float* __restrict__ w,
          const float* __restrict__ react, const float* __restrict__ prod,
          float* __restrict__ out)
{
    __shared__ __align__(16) float tile[6][TW];   // rows y0-1 .. y0+4
    __shared__ u64 wk[NK][9];    // 5*conv_weight, duplicated (v,v)
    __shared__ u64 mrk[NK];      // (-5*reactant, -5*reactant)
    __shared__ u64 pk[NK];       // (0.5*product, 0.5*product)
    __shared__ float psumh;      // 0.5 * sum(products)

    const int b   = blockIdx.y;
    const int y0  = blockIdx.x * 4;
    const int tx  = threadIdx.x;            // 0..127
    const int ty  = threadIdx.y;            // 0..1
    const int tid = ty * 128 + tx;

    // ---- stage constants (packed/duplicated for f32x2 operands) ----
    if (tid < NK * 9) {
        int k = tid / 9, t = tid - k * 9;
        float v = 5.0f * w[k * 9 + t];            // fold GAIN/2 into weights
        wk[k][t] = pack2(v, v);
    } else if (tid < NK * 10) {
        int k = tid - NK * 9;
        float v = -5.0f * react[k];               // z = 5N - 5r
        mrk[k] = pack2(v, v);
    } else if (tid < NK * 11) {
        int k = tid - NK * 10;
        float v = 0.5f * prod[k];
        pk[k] = pack2(v, v);
    } else if (tid == NK * 11) {
        float s = 0.0f;
        #pragma unroll
        for (int k = 0; k < NK; k++) s += prod[k];
        psumh = 0.5f * s;
    }

    // ---- halo columns gx=-1 and gx=512 are always zero (outside image) ----
    if (tid < 12) tile[tid >> 1][(tid & 1) ? 516 : 3] = 0.0f;

    // ---- interior tile load: 6 rows x 128 float4 = 768 / 256 thr = 3 each ----
    const float* xb = x + (size_t)b * (512 * 512);
    #pragma unroll
    for (int it = 0; it < 3; it++) {
        int i  = tid + it * 256;
        int r  = i >> 7;                  // 0..5
        int c  = (i & 127) << 2;          // 0,4,..,508
        int gy = y0 - 1 + r;
        float4 v = make_float4(0.f, 0.f, 0.f, 0.f);
        if ((unsigned)gy < 512u)
            v = *(const float4*)(xb + (size_t)gy * 512 + c);
        *(float4*)&tile[r][c + 4] = v;
    }
    __syncthreads();

    // ---- register neighborhood: 4 tile rows x 5 shifted float2 windows ----
    // row r covers tile row 2*ty + r; cols gx-1..gx+4 (gx = 4*tx).
    // Conflict-free: 3 x LDS.128 per row (16B lane stride).
    u64 nb[4][5];
    #pragma unroll
    for (int r = 0; r < 4; r++) {
        const float* trow = tile[2 * ty + r];
        float4 a = *(const float4*)&trow[4 * tx];        // need .w  (gx-1)
        float4 m = *(const float4*)&trow[4 * tx + 4];    // gx..gx+3
        float4 z = *(const float4*)&trow[4 * tx + 8];    // need .x  (gx+4)
        nb[r][0] = pack2(a.w, m.x);
        nb[r][1] = pack2(m.x, m.y);
        nb[r][2] = pack2(m.y, m.z);
        nb[r][3] = pack2(m.z, m.w);
        nb[r][4] = pack2(m.w, z.x);
    }

    const u64 MH2 = pack2(-0.5f, -0.5f);

    // accumulators: [row][pair]
    u64 aP00 = 0ull, aP01 = 0ull, aP10 = 0ull, aP11 = 0ull;  // sum(t_k * 0.5 p_k)
    u64 aT00 = 0ull, aT01 = 0ull, aT10 = 0ull, aT11 = 0ull;  // sum(-0.5 t_k)

    #pragma unroll
    for (int k = 0; k < NK; k++) {
        const u64 mk = mrk[k];
        // conv chains initialized with bias -> produce z = 5N - 5r directly
        u64 wv  = wk[k][0];
        u64 z00 = fma2(wv, nb[0][0], mk);
        u64 z01 = fma2(wv, nb[0][2], mk);
        u64 z10 = fma2(wv, nb[1][0], mk);
        u64 z11 = fma2(wv, nb[1][2], mk);
        #pragma unroll
        for (int t = 1; t < 9; t++) {
            const int r = t / 3, c = t - 3 * r;
            wv  = wk[k][t];
            z00 = fma2(wv, nb[r][c],         z00);
            z01 = fma2(wv, nb[r][c + 2],     z01);
            z10 = fma2(wv, nb[r + 1][c],     z10);
            z11 = fma2(wv, nb[r + 1][c + 2], z11);
        }
        const u64 pkk = pk[k];
        float u0, u1;
        unpack2(z00, u0, u1); u64 t00 = pack2(tanh_(u0), tanh_(u1));
        unpack2(z01, u0, u1); u64 t01 = pack2(tanh_(u0), tanh_(u1));
        unpack2(z10, u0, u1); u64 t10 = pack2(tanh_(u0), tanh_(u1));
        unpack2(z11, u0, u1); u64 t11 = pack2(tanh_(u0), tanh_(u1));
        aP00 = fma2(t00, pkk, aP00);  aT00 = fma2(t00, MH2, aT00);
        aP01 = fma2(t01, pkk, aP01);  aT01 = fma2(t01, MH2, aT01);
        aP10 = fma2(t10, pkk, aP10);  aT10 = fma2(t10, MH2, aT10);
        aP11 = fma2(t11, pkk, aP11);  aT11 = fma2(t11, MH2, aT11);
    }

    // ---- epilogue: out = clamp( 0.5*sum(p) + aP + x*(aT - 7), 0, 1 ) ----
    const float ps = psumh;
    const u64 PS2 = pack2(ps, ps);
    const u64 M72 = pack2(-7.0f, -7.0f);

    const int gy0 = y0 + 2 * ty;
    float* ob = out + (size_t)b * (512 * 512) + (size_t)gy0 * 512 + 4 * tx;

    {   // row 0: centers nb[1][1], nb[1][3]
        u64 o0 = add2_(fma2(nb[1][1], add2_(aT00, M72), aP00), PS2);
        u64 o1 = add2_(fma2(nb[1][3], add2_(aT01, M72), aP01), PS2);
        float r0, r1, r2, r3;
        unpack2(o0, r0, r1); unpack2(o1, r2, r3);
        *(float4*)ob = make_float4(__saturatef(r0), __saturatef(r1),
                                   __saturatef(r2), __saturatef(r3));
    }
    {   // row 1: centers nb[2][1], nb[2][3]
        u64 o0 = add2_(fma2(nb[2][1], add2_(aT10, M72), aP10), PS2);
        u64 o1 = add2_(fma2(nb[2][3], add2_(aT11, M72), aP11), PS2);
        float r0, r1, r2, r3;
        unpack2(o0, r0, r1); unpack2(o1, r2, r3);
        *(float4*)(ob + 512) = make_float4(__saturatef(r0), __saturatef(r1),
                                           __saturatef(r2), __saturatef(r3));
    }
}

extern "C" void kernel_launch(void* const* d_in, const int* in_sizes, int n_in,
                              void* d_out, int out_size) {
    const float* x = (const float*)d_in[0];
    const float* w = (const float*)d_in[1];
    const float* r = (const float*)d_in[2];
    const float* p = (const float*)d_in[3];
    dim3 grid(128, 16);   // 512/4 row tiles, 16 batch images
    dim3 block(128, 2);
    ca_kernel<<<grid, block>>>(x, w, r, p, (float*)d_out);
}